// round 8
// baseline (speedup 1.0000x reference)
#include <cuda_runtime.h>
#include <math.h>
#include <stdint.h>

#define Bsz 32
#define HW 65536          // H*W = 256*256
#define NPIX (Bsz * HW)
#define NBLK_MLP 296      // 2 blocks/SM * 148 SMs
#define TPB_MLP 256
#define NPXT 128          // pixels per tile

// ---- scratch (no allocations allowed) ----
__device__ float g_e[NPIX];       // exp(score) at masked pixels (others stale/unused)
__device__ int   g_list[NPIX];    // compacted full pixel indices
__device__ int   g_total;
__device__ int   g_cnt[Bsz];
__device__ float g_sumE[Bsz];
__device__ float g_sumPE[Bsz];

#define FMA_F32X2(d, a, b, c) \
    asm("fma.rn.f32x2 %0, %1, %2, %3;" : "=l"(d) : "l"(a), "l"(b), "l"(c))
#define PACK_F32X2(out, lo, hi) \
    asm("mov.b64 %0, {%1, %2};" : "=l"(out) : "r"(lo), "r"(hi))
#define UNPACK_F32X2(lo, hi, in) \
    asm("mov.b64 {%0, %1}, %2;" : "=r"(lo), "=r"(hi) : "l"(in))

__global__ void k_init() {
    int t = threadIdx.x;
    if (t < Bsz) { g_cnt[t] = 0; g_sumE[t] = 0.0f; g_sumPE[t] = 0.0f; }
    if (t == 0) g_total = 0;
}

__global__ void k_nop() {}   // launch-order pad so ncu's fixed slot lands on k_mlp

__global__ void k_compact(const int* __restrict__ zone,
                          const int* __restrict__ cats) {
    const int idx  = blockIdx.x * 256 + threadIdx.x;
    const int b    = idx >> 16;
    const int lane = threadIdx.x & 31;
    const bool m   = (zone[idx] == __ldg(&cats[b]));   // cats>=1 so zone>0 implied
    unsigned ball  = __ballot_sync(0xffffffffu, m);
    int pos = 0;
    if (lane == 0 && ball) {
        int n = __popc(ball);
        pos = atomicAdd(&g_total, n);
        atomicAdd(&g_cnt[b], n);
    }
    pos = __shfl_sync(0xffffffffu, pos, 0);
    if (m) g_list[pos + __popc(ball & ((1u << lane) - 1u))] = idx;
}

// Register-tiled GEMM: tile = 128 hidden x 128 pixels, K=64 channels.
// 256 threads; thread (tm=tid>>3, tn=tid&7) owns m=tm*4..+3, px=tn*16..+15
// as 4x8 f32x2 accumulators (32 independent FMA chains -> latency-immune).
// Features staged in SMEM (sF[k][px]); W1 streamed from global (L1-resident).
__global__ void __launch_bounds__(TPB_MLP, 2)
k_mlp(const float* __restrict__ feat,
      const float* __restrict__ pl,
      const float* __restrict__ W1,
      const float* __restrict__ b1,
      const float* __restrict__ W2,
      const float* __restrict__ b2p) {
    __shared__ __align__(16) float sF[64 * 132];   // reused as sRed[32][128] in epilogue
    __shared__ int sIdx[NPXT];

    const int tid  = threadIdx.x;
    const int lane = tid & 31;
    const int tm   = tid >> 3;    // 0..31 -> m = tm*4..+3
    const int tn   = tid & 7;     // 0..7  -> px = tn*16..+15

    // per-thread epilogue constants (fixed m across all tiles)
    float w2r[4], b1r[4];
#pragma unroll
    for (int j = 0; j < 4; j++) {
        w2r[j] = __ldg(&W2[tm * 4 + j]);
        b1r[j] = __ldg(&b1[tm * 4 + j]);
    }
    const float b2    = __ldg(b2p);
    const int   total = g_total;
    const float* w1r  = W1 + (tm * 4) * 64;   // rows m..m+3, stride 64

    for (int base = blockIdx.x * NPXT; base < total; base += NBLK_MLP * NPXT) {
        __syncthreads();   // previous tile's sRed readers done
        if (tid < NPXT) {
            int i = base + tid;
            sIdx[tid] = (i < total) ? g_list[i] : -1;
        }
        __syncthreads();

        // gather: sF[c][px], lanes on consecutive px (coalesced-ish, STS conflict-free)
#pragma unroll 4
        for (int it = 0; it < 32; it++) {
            int idx = it * 256 + tid;
            int px  = idx & 127;
            int c   = idx >> 7;
            int fi  = sIdx[px];
            float v = 0.0f;
            if (fi >= 0) {
                int bb = fi >> 16, p = fi & 65535;
                v = __ldg(feat + ((size_t)bb << 22) + ((size_t)c << 16) + p);
            }
            sF[c * 132 + px] = v;
        }
        __syncthreads();

        uint64_t acc[4][8];
#pragma unroll
        for (int j = 0; j < 4; j++)
#pragma unroll
            for (int i = 0; i < 8; i++) acc[j][i] = 0ull;

        float a[4], an[4];
#pragma unroll
        for (int j = 0; j < 4; j++) a[j] = __ldg(w1r + j * 64);

#pragma unroll 2
        for (int k = 0; k < 64; k++) {
            const int kn = (k + 1) & 63;   // wrap at 63 (extra load unused)
#pragma unroll
            for (int j = 0; j < 4; j++) an[j] = __ldg(w1r + j * 64 + kn);

            const float4* bp = (const float4*)&sF[k * 132 + tn * 16];
            float4 b0 = bp[0], b1v = bp[1], b2v = bp[2], b3v = bp[3];
            uint64_t bb[8];
            PACK_F32X2(bb[0], __float_as_uint(b0.x),  __float_as_uint(b0.y));
            PACK_F32X2(bb[1], __float_as_uint(b0.z),  __float_as_uint(b0.w));
            PACK_F32X2(bb[2], __float_as_uint(b1v.x), __float_as_uint(b1v.y));
            PACK_F32X2(bb[3], __float_as_uint(b1v.z), __float_as_uint(b1v.w));
            PACK_F32X2(bb[4], __float_as_uint(b2v.x), __float_as_uint(b2v.y));
            PACK_F32X2(bb[5], __float_as_uint(b2v.z), __float_as_uint(b2v.w));
            PACK_F32X2(bb[6], __float_as_uint(b3v.x), __float_as_uint(b3v.y));
            PACK_F32X2(bb[7], __float_as_uint(b3v.z), __float_as_uint(b3v.w));

            uint64_t ap[4];
#pragma unroll
            for (int j = 0; j < 4; j++)
                PACK_F32X2(ap[j], __float_as_uint(a[j]), __float_as_uint(a[j]));

#pragma unroll
            for (int j = 0; j < 4; j++)
#pragma unroll
                for (int i = 0; i < 8; i++)
                    FMA_F32X2(acc[j][i], ap[j], bb[i], acc[j][i]);

#pragma unroll
            for (int j = 0; j < 4; j++) a[j] = an[j];
        }

        // partial epilogue: part[n] = sum_j W2[m_j]*relu(h[m_j][n]+b1[m_j])
        float part[16];
#pragma unroll
        for (int i = 0; i < 16; i++) part[i] = 0.0f;
#pragma unroll
        for (int j = 0; j < 4; j++) {
#pragma unroll
            for (int i = 0; i < 8; i++) {
                unsigned lo, hi;
                UNPACK_F32X2(lo, hi, acc[j][i]);
                float h0 = __uint_as_float(lo) + b1r[j];
                float h1 = __uint_as_float(hi) + b1r[j];
                part[2 * i]     = fmaf(w2r[j], fmaxf(h0, 0.0f), part[2 * i]);
                part[2 * i + 1] = fmaf(w2r[j], fmaxf(h1, 0.0f), part[2 * i + 1]);
            }
        }

        __syncthreads();                 // everyone done reading sF
        float* sRed = sF;                // reuse as [32][128]
#pragma unroll
        for (int i = 0; i < 16; i++) sRed[tm * 128 + tn * 16 + i] = part[i];
        __syncthreads();

        if (tid < NPXT) {
            float sc = b2;
#pragma unroll
            for (int t = 0; t < 32; t++) sc += sRed[t * 128 + tid];

            const int fi = sIdx[tid];
            float e = 0.0f, pe = 0.0f;
            int bb = -1;
            if (fi >= 0) {
                e  = expf(sc);           // |score| is O(1): no max-subtraction needed
                pe = e * __ldg(&pl[fi]);
                g_e[fi] = e;
                bb = fi >> 16;
            }
            unsigned act = __ballot_sync(0xffffffffu, fi >= 0);
            if (act) {
                int flead = __ffs(act) - 1;
                int b0 = __shfl_sync(0xffffffffu, bb, flead);
                bool uni = __all_sync(0xffffffffu, (fi < 0) || (bb == b0));
                if (uni) {
                    float se = e, sp = pe;
#pragma unroll
                    for (int off = 16; off; off >>= 1) {
                        se += __shfl_xor_sync(0xffffffffu, se, off);
                        sp += __shfl_xor_sync(0xffffffffu, sp, off);
                    }
                    if (lane == flead) {
                        atomicAdd(&g_sumE[b0],  se);
                        atomicAdd(&g_sumPE[b0], sp);
                    }
                } else if (fi >= 0) {
                    atomicAdd(&g_sumE[bb],  e);
                    atomicAdd(&g_sumPE[bb], pe);
                }
            }
        }
    }
}

// 4 pixels per thread; vector loads (aligned bases), scalar stores (out+1 is
// only 4B-aligned -> STG.128 would trap).
__global__ void k_maps(const int* __restrict__ zone,
                       const int* __restrict__ cats,
                       float* __restrict__ out_maps) {
    const int idx4 = (blockIdx.x * 256 + threadIdx.x) * 4;
    const int b    = idx4 >> 16;
    const int cat  = __ldg(&cats[b]);
    const bool has = g_cnt[b] > 0;
    const float inv = has ? (1.0f / g_sumE[b]) : 0.0f;
    int4   z = *(const int4*)&zone[idx4];
    float4 e = *(const float4*)&g_e[idx4];
    out_maps[idx4 + 0] = (has && z.x == cat) ? e.x * inv : 0.0f;
    out_maps[idx4 + 1] = (has && z.y == cat) ? e.y * inv : 0.0f;
    out_maps[idx4 + 2] = (has && z.z == cat) ? e.z * inv : 0.0f;
    out_maps[idx4 + 3] = (has && z.w == cat) ? e.w * inv : 0.0f;
}

__global__ void k_loss(const float* __restrict__ labels,
                       float* __restrict__ out, int write_loss) {
    const int t = threadIdx.x;   // 32 threads
    float x = 0.0f;
    if (g_cnt[t] > 0) x = g_sumPE[t] / g_sumE[t];
    const float y = labels[t];
    float term = fmaxf(x, 0.0f) - x * y + log1pf(expf(-fabsf(x)));
#pragma unroll
    for (int off = 16; off; off >>= 1)
        term += __shfl_xor_sync(0xffffffffu, term, off);
    if (t == 0 && write_loss) out[0] = term / 32.0f;
}

extern "C" void kernel_launch(void* const* d_in, const int* in_sizes, int n_in,
                              void* d_out, int out_size) {
    const float* pl     = (const float*)d_in[0];  // (B,1,H,W)
    const float* feat   = (const float*)d_in[1];  // (B,C,H,W)
    const int*   zone   = (const int*)  d_in[2];  // (B,H,W)
    const int*   cats   = (const int*)  d_in[3];  // (B,)
    const float* labels = (const float*)d_in[4];  // (B,)
    const float* W1     = (const float*)d_in[5];  // (128,64)
    const float* b1     = (const float*)d_in[6];  // (128,)
    const float* W2     = (const float*)d_in[7];  // (128,)
    const float* b2     = (const float*)d_in[8];  // ()
    float* out = (float*)d_out;

    const int nmap = NPIX;
    int map_off = out_size - nmap;
    if (map_off < 0) map_off = 0;

    k_init<<<1, 32>>>();
    k_compact<<<NPIX / 256, 256>>>(zone, cats);
    k_nop<<<1, 32>>>();   // pad: keeps k_mlp in the profiled (4th) launch slot
    k_mlp<<<NBLK_MLP, TPB_MLP>>>(feat, pl, W1, b1, W2, b2);
    k_maps<<<NPIX / 1024, 256>>>(zone, cats, out + map_off);
    k_loss<<<1, 32>>>(labels, out, map_off >= 1 ? 1 : 0);
}